// round 3
// baseline (speedup 1.0000x reference)
#include <cuda_runtime.h>
#include <math.h>

#define BSZ  16      // batch
#define NCAP 1152    // primary caps
#define DP   8       // dim primary
#define DDIG 10      // digit caps
#define DD   16      // dim digit

#define TILE_N 16
#define NT (NCAP / TILE_N)   // 72

// Scratch (device globals; no allocation allowed)
__device__ float g_U[BSZ * DDIG * NCAP * DD];   // U_hat [b][d][n][j]  ~11.8 MB
__device__ float g_Asum[BSZ * DDIG * NCAP];     // A_sum [b][d][n]     ~0.74 MB

// -------------------------------------------------------------------------
// K1: votes  U_hat[b,d,n,j] = sum_i W[d,n,j,i] * u[b,n,i]
// Grid: (DDIG, NT) = 720 CTAs. Each CTA: one d, 16-wide n tile, all 16 b.
// -------------------------------------------------------------------------
__global__ __launch_bounds__(256) void k1_votes(
    const float* __restrict__ u,   // [B][N][DP]
    const float* __restrict__ W)   // [D][N][DD][DP]
{
    const int d  = blockIdx.x;
    const int n0 = blockIdx.y * TILE_N;
    const int t  = threadIdx.x;

    __shared__ __align__(16) float us[BSZ][TILE_N][DP];   // 8 KB

    // Stage u tile: 16 * 16 * 8 floats = 512 float4; 2 per thread
    #pragma unroll
    for (int it = 0; it < 2; ++it) {
        const int idx = it * 256 + t;
        const int b   = idx >> 5;       // 32 float4 per b
        const int rem = idx & 31;
        const float4 v = reinterpret_cast<const float4*>(
            u + (size_t)b * NCAP * DP + (size_t)n0 * DP)[rem];
        reinterpret_cast<float4*>(&us[b][0][0])[rem] = v;
    }
    __syncthreads();

    // One (n_local, j) per thread: 16*16 = 256 items.
    const int j  = t & 15;
    const int nl = t >> 4;
    const int n  = n0 + nl;

    const float4* wp = reinterpret_cast<const float4*>(
        W + ((size_t)(d * NCAP + n) * DD + j) * DP);
    const float4 w0 = wp[0];
    const float4 w1 = wp[1];

    #pragma unroll
    for (int b = 0; b < BSZ; ++b) {
        const float4* up = reinterpret_cast<const float4*>(&us[b][nl][0]);
        const float4 u0 = up[0];
        const float4 u1 = up[1];
        float acc = w0.x * u0.x + w0.y * u0.y + w0.z * u0.z + w0.w * u0.w
                  + w1.x * u1.x + w1.y * u1.y + w1.z * u1.z + w1.w * u1.w;
        g_U[((size_t)(b * DDIG + d) * NCAP + n) * DD + j] = acc;
    }
}

// -------------------------------------------------------------------------
// K2: per (b,d): T[j] = sum_n U[n][j], then A_sum[n] = (T . U[n]) / sqrt(8)
// Grid: (DDIG, BSZ), 1024 threads.
// -------------------------------------------------------------------------
__global__ __launch_bounds__(1024) void k2_asum()
{
    const int d = blockIdx.x;
    const int b = blockIdx.y;
    const int t = threadIdx.x;

    const float* Ubd = g_U + (size_t)(b * DDIG + d) * NCAP * DD;

    float part[DD];
    #pragma unroll
    for (int j = 0; j < DD; ++j) part[j] = 0.f;

    for (int n = t; n < NCAP; n += 1024) {
        const float4* r = reinterpret_cast<const float4*>(Ubd + (size_t)n * DD);
        const float4 v0 = r[0], v1 = r[1], v2 = r[2], v3 = r[3];
        part[0]  += v0.x; part[1]  += v0.y; part[2]  += v0.z; part[3]  += v0.w;
        part[4]  += v1.x; part[5]  += v1.y; part[6]  += v1.z; part[7]  += v1.w;
        part[8]  += v2.x; part[9]  += v2.y; part[10] += v2.z; part[11] += v2.w;
        part[12] += v3.x; part[13] += v3.y; part[14] += v3.z; part[15] += v3.w;
    }

    #pragma unroll
    for (int off = 16; off > 0; off >>= 1) {
        #pragma unroll
        for (int j = 0; j < DD; ++j)
            part[j] += __shfl_xor_sync(0xffffffffu, part[j], off);
    }

    __shared__ float wsum[32][DD];
    const int lane = t & 31, w = t >> 5;
    if (lane == 0) {
        #pragma unroll
        for (int j = 0; j < DD; ++j) wsum[w][j] = part[j];
    }
    __syncthreads();

    __shared__ float Tsh[DD];
    if (t < DD) {
        float s = 0.f;
        #pragma unroll
        for (int ww = 0; ww < 32; ++ww) s += wsum[ww][t];
        Tsh[t] = s;
    }
    __syncthreads();

    float T[DD];
    #pragma unroll
    for (int j = 0; j < DD; ++j) T[j] = Tsh[j];

    const float inv_sqrt8 = 0.3535533905932738f;
    float* As = g_Asum + (size_t)(b * DDIG + d) * NCAP;
    for (int n = t; n < NCAP; n += 1024) {
        const float4* r = reinterpret_cast<const float4*>(Ubd + (size_t)n * DD);
        const float4 v0 = r[0], v1 = r[1], v2 = r[2], v3 = r[3];
        float dot = T[0]  * v0.x + T[1]  * v0.y + T[2]  * v0.z + T[3]  * v0.w
                  + T[4]  * v1.x + T[5]  * v1.y + T[6]  * v1.z + T[7]  * v1.w
                  + T[8]  * v2.x + T[9]  * v2.y + T[10] * v2.z + T[11] * v2.w
                  + T[12] * v3.x + T[13] * v3.y + T[14] * v3.z + T[15] * v3.w;
        As[n] = dot * inv_sqrt8;
    }
}

// -------------------------------------------------------------------------
// K3: softmax over d (per b,n), S[b,d,j] = sum_n (B_prior[d,n] + C[b,d,n]) * U[b,d,n,j]
// then squash. Grid: (DDIG, BSZ), 1024 threads.
// -------------------------------------------------------------------------
__global__ __launch_bounds__(1024) void k3_out(
    const float* __restrict__ Bp,   // [D][1][N]
    float* __restrict__ out)        // [B][D][DD]
{
    const int d = blockIdx.x;
    const int b = blockIdx.y;
    const int t = threadIdx.x;

    const float* Ubd = g_U + (size_t)(b * DDIG + d) * NCAP * DD;
    const float* As  = g_Asum + (size_t)b * DDIG * NCAP;

    float s[DD];
    #pragma unroll
    for (int j = 0; j < DD; ++j) s[j] = 0.f;

    for (int n = t; n < NCAP; n += 1024) {
        float a[DDIG];
        float m = -1e30f;
        #pragma unroll
        for (int dd = 0; dd < DDIG; ++dd) {
            a[dd] = __ldg(&As[(size_t)dd * NCAP + n]);
            m = fmaxf(m, a[dd]);
        }
        float denom = 0.f;
        #pragma unroll
        for (int dd = 0; dd < DDIG; ++dd) denom += expf(a[dd] - m);
        const float c   = expf(a[d] - m) / denom;
        const float wgt = c + __ldg(&Bp[(size_t)d * NCAP + n]);

        const float4* r = reinterpret_cast<const float4*>(Ubd + (size_t)n * DD);
        const float4 v0 = r[0], v1 = r[1], v2 = r[2], v3 = r[3];
        s[0]  += wgt * v0.x; s[1]  += wgt * v0.y; s[2]  += wgt * v0.z; s[3]  += wgt * v0.w;
        s[4]  += wgt * v1.x; s[5]  += wgt * v1.y; s[6]  += wgt * v1.z; s[7]  += wgt * v1.w;
        s[8]  += wgt * v2.x; s[9]  += wgt * v2.y; s[10] += wgt * v2.z; s[11] += wgt * v2.w;
        s[12] += wgt * v3.x; s[13] += wgt * v3.y; s[14] += wgt * v3.z; s[15] += wgt * v3.w;
    }

    #pragma unroll
    for (int off = 16; off > 0; off >>= 1) {
        #pragma unroll
        for (int j = 0; j < DD; ++j)
            s[j] += __shfl_xor_sync(0xffffffffu, s[j], off);
    }

    __shared__ float wsum[32][DD];
    const int lane = t & 31, w = t >> 5;
    if (lane == 0) {
        #pragma unroll
        for (int j = 0; j < DD; ++j) wsum[w][j] = s[j];
    }
    __syncthreads();

    __shared__ float Sf[DD];
    __shared__ float coef_sh;
    if (t < DD) {
        float v = 0.f;
        #pragma unroll
        for (int ww = 0; ww < 32; ++ww) v += wsum[ww][t];
        Sf[t] = v;
    }
    __syncthreads();
    if (t == 0) {
        float nn = 0.f;
        #pragma unroll
        for (int j = 0; j < DD; ++j) nn += Sf[j] * Sf[j];
        const float norm = sqrtf(nn);
        const float EPS  = 1e-7f;
        coef_sh = (1.f - 1.f / (expf(norm) + EPS)) / (norm + EPS);
    }
    __syncthreads();
    if (t < DD) {
        out[(size_t)(b * DDIG + d) * DD + t] = coef_sh * Sf[t];
    }
}

// -------------------------------------------------------------------------
extern "C" void kernel_launch(void* const* d_in, const int* in_sizes, int n_in,
                              void* d_out, int out_size)
{
    const float* u  = (const float*)d_in[0];   // primary_caps [16,1152,8]
    const float* W  = (const float*)d_in[1];   // W            [10,1152,16,8]
    const float* Bp = (const float*)d_in[2];   // B_prior      [10,1,1152]
    float* out      = (float*)d_out;           // [16,10,16]

    (void)in_sizes; (void)n_in; (void)out_size;

    k1_votes<<<dim3(DDIG, NT), 256>>>(u, W);
    k2_asum<<<dim3(DDIG, BSZ), 1024>>>();
    k3_out<<<dim3(DDIG, BSZ), 1024>>>(Bp, out);
}

// round 4
// speedup vs baseline: 1.1648x; 1.1648x over previous
#include <cuda_runtime.h>
#include <math.h>

#define BSZ  16      // batch
#define NCAP 1152    // primary caps
#define DP   8       // dim primary
#define DDIG 10      // digit caps
#define DD   16      // dim digit

#define TILE_N 16
#define NT (NCAP / TILE_N)   // 72
#define NC3 4                // n-splits in k3
#define NSEG (NCAP / NC3)    // 288

// Scratch (device globals; fully overwritten every call — no zeroing needed)
__device__ float g_U  [BSZ * DDIG * NCAP * DD];   // U_hat [b][d][n][j]
__device__ float g_Tp [BSZ * DDIG * DD * NT];     // partial T [b][d][j][tile]
__device__ float g_wgt[BSZ * DDIG * NCAP];        // softmax+prior weight [b][d][n]
__device__ float g_Sp [BSZ * DDIG * DD * NC3];    // partial S [b][d][j][c]

// -------------------------------------------------------------------------
// K1: votes U_hat[b,d,n,j] = W[d,n,j,:]·u[b,n,:]  +  per-tile partial T
// Grid (DDIG, NT) = 720 CTAs x 256 threads.
// -------------------------------------------------------------------------
__global__ __launch_bounds__(256) void k1_votes(
    const float* __restrict__ u,   // [B][N][DP]
    const float* __restrict__ W)   // [D][N][DD][DP]
{
    const int d    = blockIdx.x;
    const int tile = blockIdx.y;
    const int n0   = tile * TILE_N;
    const int t    = threadIdx.x;
    const int j    = t & 15;
    const int nl   = t >> 4;
    const int n    = n0 + nl;
    const int lane = t & 31;
    const int w    = t >> 5;

    // Issue W DRAM loads FIRST (overlap latency with staging + sync)
    const float4* wp = reinterpret_cast<const float4*>(
        W + ((size_t)(d * NCAP + n) * DD + j) * DP);
    const float4 w0 = wp[0];
    const float4 w1 = wp[1];

    __shared__ __align__(16) float us[BSZ][TILE_N][DP];   // 8 KB
    __shared__ float red[BSZ][8][DD];                     // 8 KB

    // Stage u tile: 512 float4; 2 per thread
    #pragma unroll
    for (int it = 0; it < 2; ++it) {
        const int idx = it * 256 + t;
        const int b   = idx >> 5;       // 32 float4 per b
        const int rem = idx & 31;
        const float4 v = reinterpret_cast<const float4*>(
            u + (size_t)b * NCAP * DP + (size_t)n0 * DP)[rem];
        reinterpret_cast<float4*>(&us[b][0][0])[rem] = v;
    }
    __syncthreads();

    #pragma unroll
    for (int b = 0; b < BSZ; ++b) {
        const float4* up = reinterpret_cast<const float4*>(&us[b][nl][0]);
        const float4 u0 = up[0];
        const float4 u1 = up[1];
        const float acc = w0.x * u0.x + w0.y * u0.y + w0.z * u0.z + w0.w * u0.w
                        + w1.x * u1.x + w1.y * u1.y + w1.z * u1.z + w1.w * u1.w;
        g_U[((size_t)(b * DDIG + d) * NCAP + n) * DD + j] = acc;

        // partial T over nl: warp w holds nl = {2w, 2w+1}; xor16 pairs them
        const float ps = acc + __shfl_xor_sync(0xffffffffu, acc, 16);
        if (lane < 16) red[b][w][lane] = ps;   // lane == j for nl even
    }
    __syncthreads();

    // 256 threads -> (b, j): sum 8 warp partials, store tile partial
    {
        const int b2 = t >> 4;
        const int j2 = t & 15;
        float s = 0.f;
        #pragma unroll
        for (int ww = 0; ww < 8; ++ww) s += red[b2][ww][j2];
        g_Tp[((size_t)(b2 * DDIG + d) * DD + j2) * NT + tile] = s;
    }
}

// -------------------------------------------------------------------------
// K2: per (b,n): a[d] = T[b,d,:]·U[b,d,n,:]/sqrt(8); softmax over d;
//     wgt[b,d,n] = C + B_prior[d,n]. Pure streaming, no reductions.
// Grid (BSZ, NCAP/128) = (16, 9) x 128 threads.
// -------------------------------------------------------------------------
__global__ __launch_bounds__(128) void k2_wgt(
    const float* __restrict__ Bp)   // [D][1][N]
{
    const int b  = blockIdx.x;
    const int ch = blockIdx.y;
    const int t  = threadIdx.x;

    __shared__ float Tsm[DDIG][DD];

    // Build T[b,d,j] from 72 contiguous tile partials (float4-vectorized)
    for (int idx = t; idx < DDIG * DD; idx += 128) {
        const float4* p = reinterpret_cast<const float4*>(
            &g_Tp[(size_t)(b * DDIG * DD + idx) * NT]);
        float s = 0.f;
        #pragma unroll
        for (int k = 0; k < NT / 4; ++k) {
            const float4 v = p[k];
            s += v.x + v.y + v.z + v.w;
        }
        Tsm[idx >> 4][idx & 15] = s;
    }
    __syncthreads();

    const int n = ch * 128 + t;
    const float inv_sqrt8 = 0.3535533905932738f;

    float a[DDIG];
    #pragma unroll
    for (int d = 0; d < DDIG; ++d) {
        const float4* r = reinterpret_cast<const float4*>(
            g_U + ((size_t)(b * DDIG + d) * NCAP + n) * DD);
        const float4 v0 = r[0], v1 = r[1], v2 = r[2], v3 = r[3];
        const float* T = Tsm[d];
        a[d] = (T[0]  * v0.x + T[1]  * v0.y + T[2]  * v0.z + T[3]  * v0.w
              + T[4]  * v1.x + T[5]  * v1.y + T[6]  * v1.z + T[7]  * v1.w
              + T[8]  * v2.x + T[9]  * v2.y + T[10] * v2.z + T[11] * v2.w
              + T[12] * v3.x + T[13] * v3.y + T[14] * v3.z + T[15] * v3.w)
              * inv_sqrt8;
    }

    float m = a[0];
    #pragma unroll
    for (int d = 1; d < DDIG; ++d) m = fmaxf(m, a[d]);
    float e[DDIG], denom = 0.f;
    #pragma unroll
    for (int d = 0; d < DDIG; ++d) { e[d] = __expf(a[d] - m); denom += e[d]; }
    const float rden = 1.f / denom;

    #pragma unroll
    for (int d = 0; d < DDIG; ++d) {
        g_wgt[((size_t)(b * DDIG + d)) * NCAP + n] =
            e[d] * rden + __ldg(&Bp[(size_t)d * NCAP + n]);
    }
}

// -------------------------------------------------------------------------
// K3: partial S[b,d,j] over an n-segment of 288.
// Grid (160, NC3) = 640 CTAs x 128 threads (16 j x 8 sub).
// -------------------------------------------------------------------------
__global__ __launch_bounds__(128) void k3_spart()
{
    const int bd  = blockIdx.x;     // b*DDIG + d
    const int c   = blockIdx.y;
    const int t   = threadIdx.x;
    const int j   = t & 15;
    const int sub = t >> 4;         // 0..7
    const int lane = t & 31;
    const int w    = t >> 5;        // 0..3

    const float* Ubd = g_U   + (size_t)bd * NCAP * DD;
    const float* wg  = g_wgt + (size_t)bd * NCAP;
    const int nbase  = c * NSEG;

    float s = 0.f;
    #pragma unroll 4
    for (int k = 0; k < NSEG / 8; ++k) {       // 36 iters
        const int n = nbase + k * 8 + sub;
        s += wg[n] * Ubd[(size_t)n * DD + j];
    }

    // reduce over sub: xor16 pairs sub within warp, then 4-warp smem reduce
    s += __shfl_xor_sync(0xffffffffu, s, 16);
    __shared__ float red[4][DD];
    if (lane < 16) red[w][lane] = s;
    __syncthreads();
    if (t < DD) {
        const float v = red[0][t] + red[1][t] + red[2][t] + red[3][t];
        g_Sp[((size_t)bd * DD + t) * NC3 + c] = v;
    }
}

// -------------------------------------------------------------------------
// K4: final S + squash. Grid (BSZ) x 160 threads (d,j).
// -------------------------------------------------------------------------
__global__ __launch_bounds__(160) void k4_out(float* __restrict__ out)
{
    const int b = blockIdx.x;
    const int t = threadIdx.x;      // 0..159
    const int d = t >> 4;
    const int j = t & 15;

    __shared__ float S[DDIG][DD];
    __shared__ float coef[DDIG];

    const float4 v = *reinterpret_cast<const float4*>(
        &g_Sp[(size_t)(b * DDIG * DD + t) * NC3]);
    S[d][j] = v.x + v.y + v.z + v.w;
    __syncthreads();

    if (t < DDIG) {
        float nn = 0.f;
        #pragma unroll
        for (int jj = 0; jj < DD; ++jj) nn += S[t][jj] * S[t][jj];
        const float norm = sqrtf(nn);
        const float EPS  = 1e-7f;
        coef[t] = (1.f - 1.f / (__expf(norm) + EPS)) / (norm + EPS);
    }
    __syncthreads();

    out[(size_t)b * DDIG * DD + t] = coef[d] * S[d][j];
}

// -------------------------------------------------------------------------
extern "C" void kernel_launch(void* const* d_in, const int* in_sizes, int n_in,
                              void* d_out, int out_size)
{
    const float* u  = (const float*)d_in[0];   // primary_caps [16,1152,8]
    const float* W  = (const float*)d_in[1];   // W            [10,1152,16,8]
    const float* Bp = (const float*)d_in[2];   // B_prior      [10,1,1152]
    float* out      = (float*)d_out;           // [16,10,16]

    (void)in_sizes; (void)n_in; (void)out_size;

    k1_votes<<<dim3(DDIG, NT), 256>>>(u, W);
    k2_wgt  <<<dim3(BSZ, NCAP / 128), 128>>>(Bp);
    k3_spart<<<dim3(BSZ * DDIG, NC3), 128>>>();
    k4_out  <<<BSZ, 160>>>(out);
}